// round 9
// baseline (speedup 1.0000x reference)
#include <cuda_runtime.h>
#include <cuda_bf16.h>
#include <math.h>
#include <cstdint>

#define T_  1024
#define C_  1024
#define H_  16
#define HD_ 64
#define B_  4
#define C3_ 3072

// ---------------- scratch (device globals; allocation-free) ----------------
__device__ float g_qkv[(size_t)B_ * T_ * C3_];

__device__ __nv_bfloat16 g_xh[(size_t)B_ * T_ * C_];
__device__ __nv_bfloat16 g_xl[(size_t)B_ * T_ * C_];
__device__ __nv_bfloat16 g_yh[(size_t)B_ * T_ * C_];
__device__ __nv_bfloat16 g_yl[(size_t)B_ * T_ * C_];
__device__ __nv_bfloat16 g_wah[(size_t)C3_ * C_];
__device__ __nv_bfloat16 g_wal[(size_t)C3_ * C_];
__device__ __nv_bfloat16 g_wph[(size_t)C_ * C_];
__device__ __nv_bfloat16 g_wpl[(size_t)C_ * C_];

// per-head split arrays: [bh][t][d] for q,k ; [bh][d][t] for v ; [h][r][d] for E
__device__ __nv_bfloat16 g_qh[(size_t)B_ * H_ * T_ * HD_];
__device__ __nv_bfloat16 g_ql[(size_t)B_ * H_ * T_ * HD_];
__device__ __nv_bfloat16 g_kh[(size_t)B_ * H_ * T_ * HD_];
__device__ __nv_bfloat16 g_kl[(size_t)B_ * H_ * T_ * HD_];
__device__ __nv_bfloat16 g_vth[(size_t)B_ * H_ * HD_ * T_];
__device__ __nv_bfloat16 g_vtl[(size_t)B_ * H_ * HD_ * T_];
__device__ __nv_bfloat16 g_eh[(size_t)H_ * T_ * HD_];

// ---------------- warp MMA helpers (baseline PTX) ----------------
__device__ __forceinline__ uint32_t smem_u32(const void* p) {
    uint32_t a;
    asm("{ .reg .u64 t; cvta.to.shared.u64 t, %1; cvt.u32.u64 %0, t; }" : "=r"(a) : "l"(p));
    return a;
}
__device__ __forceinline__ void ldsm4(uint32_t* r, uint32_t addr) {
    asm volatile("ldmatrix.sync.aligned.m8n8.x4.shared.b16 {%0,%1,%2,%3}, [%4];"
                 : "=r"(r[0]), "=r"(r[1]), "=r"(r[2]), "=r"(r[3]) : "r"(addr));
}
__device__ __forceinline__ void mma16816(float* c, const uint32_t* a, const uint32_t* b) {
    asm volatile("mma.sync.aligned.m16n8k16.row.col.f32.bf16.bf16.f32 "
                 "{%0,%1,%2,%3}, {%4,%5,%6,%7}, {%8,%9}, {%0,%1,%2,%3};"
                 : "+f"(c[0]), "+f"(c[1]), "+f"(c[2]), "+f"(c[3])
                 : "r"(a[0]), "r"(a[1]), "r"(a[2]), "r"(a[3]), "r"(b[0]), "r"(b[1]));
}
__device__ __forceinline__ void cp16(uint32_t dst, const void* src) {
    asm volatile("cp.async.cg.shared.global [%0], [%1], 16;" :: "r"(dst), "l"(src));
}
#define CP_COMMIT() asm volatile("cp.async.commit_group;" ::: "memory")
#define CP_WAIT(n)  asm volatile("cp.async.wait_group %0;" :: "n"(n) : "memory")

__device__ __forceinline__ __nv_bfloat162 split_hi2(float a, float b) {
    return __nv_bfloat162(__float2bfloat16(a), __float2bfloat16(b));
}
__device__ __forceinline__ __nv_bfloat162 split_lo2(float a, float b) {
    __nv_bfloat16 ha = __float2bfloat16(a), hb = __float2bfloat16(b);
    return __nv_bfloat162(__float2bfloat16(a - __bfloat162float(ha)),
                          __float2bfloat16(b - __bfloat162float(hb)));
}

// ---------------------------------------------------------------------------
// Split-bf16 HMMA GEMM, cp.async double-buffered.
// out[M,N] = A@B^T + bias. Tile 128x128, Kc=32, 2 stages.
// ---------------------------------------------------------------------------
#define PITCH 40
#define TILE_ELEMS (128 * PITCH)
#define STAGE_BYTES (4 * TILE_ELEMS * 2)          // 4 tiles of 128x32 bf16 (pitch 40)
#define GEMM_SMEM_BYTES (2 * STAGE_BYTES)         // 81920

__global__ __launch_bounds__(256, 2)
void gemm_mma_kernel(const __nv_bfloat16* __restrict__ Ah, const __nv_bfloat16* __restrict__ Al,
                     const __nv_bfloat16* __restrict__ Bh, const __nv_bfloat16* __restrict__ Bl,
                     const float* __restrict__ bias, float* __restrict__ out,
                     int M, int N, int K)
{
    extern __shared__ char gsm[];
    const uint32_t sb0 = smem_u32(gsm);

    const int tid = threadIdx.x;
    const int wid = tid >> 5, lane = tid & 31;
    const int wr = wid >> 2, wc = wid & 3;
    const int m0 = blockIdx.y * 128, n0g = blockIdx.x * 128;

    float acc[4][4][4];
#pragma unroll
    for (int mt = 0; mt < 4; ++mt)
#pragma unroll
        for (int nt = 0; nt < 4; ++nt)
#pragma unroll
            for (int i = 0; i < 4; ++i) acc[mt][nt][i] = 0.f;

    const int a_row = (lane & 15);
    const int a_col = (lane >> 4) << 3;
    const int b_row = (lane & 7) + ((lane >> 4) << 3);
    const int b_col = (lane & 8);

    const char* gsrc[4] = {
        (const char*)(Ah + (size_t)m0 * K),
        (const char*)(Al + (size_t)m0 * K),
        (const char*)(Bh + (size_t)n0g * K),
        (const char*)(Bl + (size_t)n0g * K) };
    const size_t rowb = (size_t)K * 2;

    // loader: this thread's fixed (row, col16) within each 128x32 tile
    const int lr = tid >> 1;              // 0..127
    const int lc0 = (tid & 1) * 2;        // 0 or 2 (two 16B units per thread)
    const int nch = K / 32;

    // prologue: stage chunk 0
    {
        const uint32_t stg = sb0;
#pragma unroll
        for (int t = 0; t < 4; ++t) {
            const char* src = gsrc[t] + (size_t)lr * rowb + lc0 * 16;
            uint32_t dst = stg + t * (TILE_ELEMS * 2) + lr * (PITCH * 2) + lc0 * 16;
            cp16(dst, src);
            cp16(dst + 16, src + 16);
        }
        CP_COMMIT();
    }

    for (int ch = 0; ch < nch; ++ch) {
        if (ch + 1 < nch) {
            const uint32_t stg = sb0 + ((ch + 1) & 1) * STAGE_BYTES;
            const size_t kb = (size_t)(ch + 1) * 64;
#pragma unroll
            for (int t = 0; t < 4; ++t) {
                const char* src = gsrc[t] + kb + (size_t)lr * rowb + lc0 * 16;
                uint32_t dst = stg + t * (TILE_ELEMS * 2) + lr * (PITCH * 2) + lc0 * 16;
                cp16(dst, src);
                cp16(dst + 16, src + 16);
            }
            CP_COMMIT();
            CP_WAIT(1);
        } else {
            CP_WAIT(0);
        }
        __syncthreads();

        const uint32_t sbuf = sb0 + (ch & 1) * STAGE_BYTES;
        const uint32_t sAh = sbuf, sAl = sbuf + TILE_ELEMS * 2,
                       sBh = sbuf + 2 * TILE_ELEMS * 2, sBl = sbuf + 3 * TILE_ELEMS * 2;

#pragma unroll
        for (int ks = 0; ks < 2; ++ks) {
            const int kofs = ks * 16;
            uint32_t Af[4][4], Bf[2][4];
#pragma unroll
            for (int mt = 0; mt < 4; ++mt)
                ldsm4(Af[mt], sAh + ((wr * 64 + mt * 16 + a_row) * PITCH + kofs + a_col) * 2);
#pragma unroll
            for (int nt2 = 0; nt2 < 2; ++nt2)
                ldsm4(Bf[nt2], sBl + ((wc * 32 + nt2 * 16 + b_row) * PITCH + kofs + b_col) * 2);
#pragma unroll
            for (int mt = 0; mt < 4; ++mt)
#pragma unroll
                for (int nt = 0; nt < 4; ++nt)
                    mma16816(acc[mt][nt], Af[mt], &Bf[nt >> 1][(nt & 1) * 2]);

#pragma unroll
            for (int nt2 = 0; nt2 < 2; ++nt2)
                ldsm4(Bf[nt2], sBh + ((wc * 32 + nt2 * 16 + b_row) * PITCH + kofs + b_col) * 2);
#pragma unroll
            for (int mt = 0; mt < 4; ++mt)
#pragma unroll
                for (int nt = 0; nt < 4; ++nt)
                    mma16816(acc[mt][nt], Af[mt], &Bf[nt >> 1][(nt & 1) * 2]);

#pragma unroll
            for (int mt = 0; mt < 4; ++mt)
                ldsm4(Af[mt], sAl + ((wr * 64 + mt * 16 + a_row) * PITCH + kofs + a_col) * 2);
#pragma unroll
            for (int mt = 0; mt < 4; ++mt)
#pragma unroll
                for (int nt = 0; nt < 4; ++nt)
                    mma16816(acc[mt][nt], Af[mt], &Bf[nt >> 1][(nt & 1) * 2]);
        }
        __syncthreads();
    }

    const int qr = lane >> 2, qc = (lane & 3) * 2;
#pragma unroll
    for (int mt = 0; mt < 4; ++mt) {
        const int row = m0 + wr * 64 + mt * 16 + qr;
#pragma unroll
        for (int nt = 0; nt < 4; ++nt) {
            const int col = n0g + wc * 32 + nt * 8 + qc;
            const float b0 = bias[col], b1 = bias[col + 1];
            float2 o0 = {acc[mt][nt][0] + b0, acc[mt][nt][1] + b1};
            float2 o1 = {acc[mt][nt][2] + b0, acc[mt][nt][3] + b1};
            *(float2*)&out[(size_t)row * N + col] = o0;
            *(float2*)&out[(size_t)(row + 8) * N + col] = o1;
        }
    }
}

// ---------------------------------------------------------------------------
// MMA flash attention with rel-pos (unchanged from R7 winner).
// grid (64 bh, 16 i-tiles), 128 threads (4 warps). i-tile 64, j-tile 64.
// ---------------------------------------------------------------------------
#define PA 72      // bf16 smem pitch (elements); row = 144 B
#define PS2 66     // fp32 pitch for S2 band

#define SO_QE  0
#define SO_QL  9216
#define SO_K   18432
#define SO_KL  27648
#define SO_V   36864
#define SO_VL  46080
#define SO_S2  55296
#define SO_P   89088
#define SO_PL  98304
#define ATTN_SMEM_BYTES 107520

__global__ __launch_bounds__(128, 2)
void attn_mma_kernel()
{
    extern __shared__ char sm[];
    const uint32_t sb = smem_u32(sm);
    float* s2f = (float*)(sm + SO_S2);

    const int tid = threadIdx.x, lane = tid & 31, w = tid >> 5;
    const int bh = blockIdx.x, h = bh & 15, b = bh >> 4;
    const int it = 15 - (int)blockIdx.y, i0 = it * 64;

    const int qr = lane >> 2, qc = (lane & 3) * 2;
    const int a_row = lane & 15, a_col = (lane >> 4) << 3;
    const int b_row = (lane & 7) + ((lane >> 4) << 3), b_col = lane & 8;

    // ---- stage Q (hi/lo) and load Q frags once ----
    {
        const char* sqh = (const char*)(g_qh + ((size_t)bh * T_ + i0) * HD_);
        const char* sql = (const char*)(g_ql + ((size_t)bh * T_ + i0) * HD_);
#pragma unroll
        for (int u = 0; u < 4; ++u) {
            int idx = u * 128 + tid;
            int r = idx >> 3, c = idx & 7;
            *(uint4*)(sm + SO_QE + r * 144 + c * 16) = *(const uint4*)(sqh + r * 128 + c * 16);
            *(uint4*)(sm + SO_QL + r * 144 + c * 16) = *(const uint4*)(sql + r * 128 + c * 16);
        }
    }
    __syncthreads();
    uint32_t Aqh[4][4], Aql[4][4];
#pragma unroll
    for (int ks = 0; ks < 4; ++ks) {
        ldsm4(Aqh[ks], sb + SO_QE + ((w * 16 + a_row) * PA + ks * 16 + a_col) * 2);
        ldsm4(Aql[ks], sb + SO_QL + ((w * 16 + a_row) * PA + ks * 16 + a_col) * 2);
    }

    float o[8][4];
#pragma unroll
    for (int nt = 0; nt < 8; ++nt)
#pragma unroll
        for (int e = 0; e < 4; ++e) o[nt][e] = 0.f;
    float m0r = -1e30f, m1r = -1e30f, l0r = 0.f, l1r = 0.f;

    const int iiA = w * 16 + qr, iiB = iiA + 8;

    for (int jt = 0; jt <= it; ++jt) {
        const int j0 = jt * 64;
        const int delta = i0 - j0;
        __syncthreads();   // smem free: Q frags done / prev PV done

        // ---- load K, V, E tiles ----
        {
            const char* kh = (const char*)(g_kh + ((size_t)bh * T_ + j0) * HD_);
            const char* kl = (const char*)(g_kl + ((size_t)bh * T_ + j0) * HD_);
#pragma unroll
            for (int u = 0; u < 4; ++u) {
                int idx = u * 128 + tid;
                int r = idx >> 3, c = idx & 7;
                *(uint4*)(sm + SO_K  + r * 144 + c * 16) = *(const uint4*)(kh + r * 128 + c * 16);
                *(uint4*)(sm + SO_KL + r * 144 + c * 16) = *(const uint4*)(kl + r * 128 + c * 16);
            }
            const char* vh = (const char*)(g_vth + (size_t)bh * HD_ * T_ + j0);
            const char* vl = (const char*)(g_vtl + (size_t)bh * HD_ * T_ + j0);
#pragma unroll
            for (int u = 0; u < 4; ++u) {
                int idx = u * 128 + tid;
                int r = idx >> 3, c = idx & 7;   // r = d row; global row stride = T_*2 bytes
                *(uint4*)(sm + SO_V  + r * 144 + c * 16) = *(const uint4*)(vh + (size_t)r * (T_ * 2) + c * 16);
                *(uint4*)(sm + SO_VL + r * 144 + c * 16) = *(const uint4*)(vl + (size_t)r * (T_ * 2) + c * 16);
            }
            const char* ep = (const char*)(g_eh + (size_t)h * T_ * HD_);
#pragma unroll
            for (int u = 0; u < 8; ++u) {
                int idx = u * 128 + tid;
                int r = idx >> 3, c = idx & 7;
                int er = delta - 63 + r;
                er = min(max(er, 0), T_ - 1);
                *(uint4*)(sm + SO_QE + r * 144 + c * 16) = *(const uint4*)(ep + (size_t)er * 128 + c * 16);
            }
        }
        __syncthreads();

        // ---- phase A: S2 = E(128x64) @ K^T, store to smem ----
        {
            float s2a[2][8][4];
#pragma unroll
            for (int mt = 0; mt < 2; ++mt)
#pragma unroll
                for (int nt = 0; nt < 8; ++nt)
#pragma unroll
                    for (int e = 0; e < 4; ++e) s2a[mt][nt][e] = 0.f;
#pragma unroll
            for (int ks = 0; ks < 4; ++ks) {
                uint32_t Ea[2][4], Kb[4][4];
#pragma unroll
                for (int mt = 0; mt < 2; ++mt)
                    ldsm4(Ea[mt], sb + SO_QE + ((w * 32 + mt * 16 + a_row) * PA + ks * 16 + a_col) * 2);
#pragma unroll
                for (int nt2 = 0; nt2 < 4; ++nt2)
                    ldsm4(Kb[nt2], sb + SO_K + ((nt2 * 16 + b_row) * PA + ks * 16 + b_col) * 2);
#pragma unroll
                for (int mt = 0; mt < 2; ++mt)
#pragma unroll
                    for (int nt = 0; nt < 8; ++nt)
                        mma16816(s2a[mt][nt], Ea[mt], &Kb[nt >> 1][(nt & 1) * 2]);
            }
#pragma unroll
            for (int mt = 0; mt < 2; ++mt) {
                const int r0 = w * 32 + mt * 16 + qr;
#pragma unroll
                for (int nt = 0; nt < 8; ++nt) {
                    const int col = nt * 8 + qc;
                    *(float2*)(s2f + r0 * PS2 + col) = make_float2(s2a[mt][nt][0], s2a[mt][nt][1]);
                    *(float2*)(s2f + (r0 + 8) * PS2 + col) = make_float2(s2a[mt][nt][2], s2a[mt][nt][3]);
                }
            }
        }

        // ---- phase B: S1 = Q @ K^T (3-term split) ----
        float p[8][4];
#pragma unroll
        for (int nt = 0; nt < 8; ++nt)
#pragma unroll
            for (int e = 0; e < 4; ++e) p[nt][e] = 0.f;
#pragma unroll
        for (int ks = 0; ks < 4; ++ks) {
            uint32_t Kbh[4][4], Kbl[4][4];
#pragma unroll
            for (int nt2 = 0; nt2 < 4; ++nt2) {
                ldsm4(Kbh[nt2], sb + SO_K  + ((nt2 * 16 + b_row) * PA + ks * 16 + b_col) * 2);
                ldsm4(Kbl[nt2], sb + SO_KL + ((nt2 * 16 + b_row) * PA + ks * 16 + b_col) * 2);
            }
#pragma unroll
            for (int nt = 0; nt < 8; ++nt) {
                mma16816(p[nt], Aqh[ks], &Kbh[nt >> 1][(nt & 1) * 2]);
                mma16816(p[nt], Aqh[ks], &Kbl[nt >> 1][(nt & 1) * 2]);
                mma16816(p[nt], Aql[ks], &Kbh[nt >> 1][(nt & 1) * 2]);
            }
        }
        __syncthreads();   // s2 visible to all

        // ---- softmax: gather S2, scale, mask, online update ----
        const bool diag = (jt == it);
        float mx0 = -1e30f, mx1 = -1e30f;
#pragma unroll
        for (int nt = 0; nt < 8; ++nt) {
            const int jj0 = nt * 8 + qc;
            float v0 = (p[nt][0] + s2f[(63 + iiA - jj0) * PS2 + jj0]) * 0.125f;
            float v1 = (p[nt][1] + s2f[(62 + iiA - jj0) * PS2 + jj0 + 1]) * 0.125f;
            float v2 = (p[nt][2] + s2f[(63 + iiB - jj0) * PS2 + jj0]) * 0.125f;
            float v3 = (p[nt][3] + s2f[(62 + iiB - jj0) * PS2 + jj0 + 1]) * 0.125f;
            if (diag) {
                if (jj0 > iiA) v0 = -1e30f;
                if (jj0 + 1 > iiA) v1 = -1e30f;
                if (jj0 > iiB) v2 = -1e30f;
                if (jj0 + 1 > iiB) v3 = -1e30f;
            }
            p[nt][0] = v0; p[nt][1] = v1; p[nt][2] = v2; p[nt][3] = v3;
            mx0 = fmaxf(mx0, fmaxf(v0, v1));
            mx1 = fmaxf(mx1, fmaxf(v2, v3));
        }
        mx0 = fmaxf(mx0, __shfl_xor_sync(0xffffffffu, mx0, 1));
        mx0 = fmaxf(mx0, __shfl_xor_sync(0xffffffffu, mx0, 2));
        mx1 = fmaxf(mx1, __shfl_xor_sync(0xffffffffu, mx1, 1));
        mx1 = fmaxf(mx1, __shfl_xor_sync(0xffffffffu, mx1, 2));
        const float mn0 = fmaxf(m0r, mx0), mn1 = fmaxf(m1r, mx1);
        const float c0 = __expf(m0r - mn0), c1 = __expf(m1r - mn1);
        float s0 = 0.f, s1s = 0.f;
#pragma unroll
        for (int nt = 0; nt < 8; ++nt) {
            p[nt][0] = __expf(p[nt][0] - mn0);
            p[nt][1] = __expf(p[nt][1] - mn0);
            p[nt][2] = __expf(p[nt][2] - mn1);
            p[nt][3] = __expf(p[nt][3] - mn1);
            s0 += p[nt][0] + p[nt][1];
            s1s += p[nt][2] + p[nt][3];
        }
        s0 += __shfl_xor_sync(0xffffffffu, s0, 1);
        s0 += __shfl_xor_sync(0xffffffffu, s0, 2);
        s1s += __shfl_xor_sync(0xffffffffu, s1s, 1);
        s1s += __shfl_xor_sync(0xffffffffu, s1s, 2);
        l0r = l0r * c0 + s0;
        l1r = l1r * c1 + s1s;
        m0r = mn0; m1r = mn1;
#pragma unroll
        for (int nt = 0; nt < 8; ++nt) {
            o[nt][0] *= c0; o[nt][1] *= c0;
            o[nt][2] *= c1; o[nt][3] *= c1;
        }
        // write P (hi/lo bf16) to smem
#pragma unroll
        for (int nt = 0; nt < 8; ++nt) {
            const int col = nt * 8 + qc;
            *(__nv_bfloat162*)(sm + SO_P  + (iiA * PA + col) * 2) = split_hi2(p[nt][0], p[nt][1]);
            *(__nv_bfloat162*)(sm + SO_PL + (iiA * PA + col) * 2) = split_lo2(p[nt][0], p[nt][1]);
            *(__nv_bfloat162*)(sm + SO_P  + (iiB * PA + col) * 2) = split_hi2(p[nt][2], p[nt][3]);
            *(__nv_bfloat162*)(sm + SO_PL + (iiB * PA + col) * 2) = split_lo2(p[nt][2], p[nt][3]);
        }
        __syncthreads();   // P visible

        // ---- PV: O += P @ V (3-term) ----
#pragma unroll
        for (int ks = 0; ks < 4; ++ks) {
            uint32_t Ap[4], Apl[4], Vb[4][4], Vbl[4][4];
            ldsm4(Ap,  sb + SO_P  + ((w * 16 + a_row) * PA + ks * 16 + a_col) * 2);
            ldsm4(Apl, sb + SO_PL + ((w * 16 + a_row) * PA + ks * 16 + a_col) * 2);
#pragma unroll
            for (int nt2 = 0; nt2 < 4; ++nt2) {
                ldsm4(Vb[nt2],  sb + SO_V  + ((nt2 * 16 + b_row) * PA + ks * 16 + b_col) * 2);
                ldsm4(Vbl[nt2], sb + SO_VL + ((nt2 * 16 + b_row) * PA + ks * 16 + b_col) * 2);
            }
#pragma unroll
            for (int nt = 0; nt < 8; ++nt) {
                mma16816(o[nt], Ap,  &Vb[nt >> 1][(nt & 1) * 2]);
                mma16816(o[nt], Ap,  &Vbl[nt >> 1][(nt & 1) * 2]);
                mma16816(o[nt], Apl, &Vb[nt >> 1][(nt & 1) * 2]);
            }
        }
    }

    // ---- write y (split bf16 directly) ----
    const float iv0 = 1.f / l0r, iv1 = 1.f / l1r;
    const size_t rowA = (size_t)b * T_ + i0 + iiA;
    const size_t rowB = rowA + 8;
#pragma unroll
    for (int nt = 0; nt < 8; ++nt) {
        const int col = h * HD_ + nt * 8 + qc;
        float v0 = o[nt][0] * iv0, v1 = o[nt][1] * iv0;
        float v2 = o[nt][2] * iv1, v3 = o[nt][3] * iv1;
        ((__nv_bfloat162*)g_yh)[(rowA * C_ + col) >> 1] = split_hi2(v0, v1);
        ((__nv_bfloat162*)g_yl)[(rowA * C_ + col) >> 1] = split_lo2(v0, v1);
        ((__nv_bfloat162*)g_yh)[(rowB * C_ + col) >> 1] = split_hi2(v2, v3);
        ((__nv_bfloat162*)g_yl)[(rowB * C_ + col) >> 1] = split_lo2(v2, v3);
    }
}

// ---------------------------------------------------------------------------
// Prep kernels
// ---------------------------------------------------------------------------
__global__ void split_kernel(const float* __restrict__ src,
                             __nv_bfloat16* __restrict__ hi,
                             __nv_bfloat16* __restrict__ lo, int n4)
{
    int i = blockIdx.x * blockDim.x + threadIdx.x;
    if (i >= n4) return;
    float4 v = *(const float4*)(src + (size_t)i * 4);
    ((__nv_bfloat162*)hi)[i * 2 + 0] = split_hi2(v.x, v.y);
    ((__nv_bfloat162*)hi)[i * 2 + 1] = split_hi2(v.z, v.w);
    ((__nv_bfloat162*)lo)[i * 2 + 0] = split_lo2(v.x, v.y);
    ((__nv_bfloat162*)lo)[i * 2 + 1] = split_lo2(v.z, v.w);
}

__global__ void transpose_split_kernel(const float* __restrict__ W,
                                       __nv_bfloat16* __restrict__ th,
                                       __nv_bfloat16* __restrict__ tl, int K, int N)
{
    __shared__ float tile[32][33];
    const int tx = threadIdx.x, ty = threadIdx.y;
    const int n0 = blockIdx.x * 32, k0 = blockIdx.y * 32;
#pragma unroll
    for (int j = 0; j < 4; ++j)
        tile[ty + j * 8][tx] = W[(size_t)(k0 + ty + j * 8) * N + n0 + tx];
    __syncthreads();
#pragma unroll
    for (int j = 0; j < 4; ++j) {
        float v = tile[tx][ty + j * 8];
        __nv_bfloat16 hh = __float2bfloat16(v);
        __nv_bfloat16 ll = __float2bfloat16(v - __bfloat162float(hh));
        size_t o = (size_t)(n0 + ty + j * 8) * K + k0 + tx;
        th[o] = hh; tl[o] = ll;
    }
}

// split qkv into per-head q/k (row) and v (transposed) bf16 hi/lo
__global__ __launch_bounds__(256)
void qkv_split_kernel()
{
    __shared__ float sv[64][65];
    const int tid = threadIdx.x;
    const int bh = blockIdx.y, t0 = blockIdx.x * 64;
    const int b = bh >> 4, h = bh & 15;
    const float* src = g_qkv + ((size_t)(b * T_ + t0)) * C3_ + h * HD_;

#pragma unroll
    for (int u = 0; u < 4; ++u) {
        int idx = u * 256 + tid;
        int r = idx >> 4, c = idx & 15;      // c in float4 units
        float4 q4 = *(const float4*)(src + (size_t)r * C3_ + c * 4);
        float4 k4 = *(const float4*)(src + (size_t)r * C3_ + C_ + c * 4);
        float4 v4 = *(const float4*)(src + (size_t)r * C3_ + 2 * C_ + c * 4);
        size_t oq = (((size_t)bh * T_ + t0 + r) * HD_ + c * 4) >> 1;  // bf162 units
        ((__nv_bfloat162*)g_qh)[oq + 0] = split_hi2(q4.x, q4.y);
        ((__nv_bfloat162*)g_qh)[oq + 1] = split_hi2(q4.z, q4.w);
        ((__nv_bfloat162*)g_ql)[oq + 0] = split_lo2(q4.x, q4.y);
        ((__nv_bfloat162*)g_ql)[oq + 1] = split_lo2(q4.z, q4.w);
        ((__nv_bfloat162*)g_kh)[oq + 0] = split_hi2(k4.x, k4.y);
        ((__nv_bfloat162*)g_kh)[oq + 1] = split_hi2(k4.z, k4.w);
        ((__nv_bfloat162*)g_kl)[oq + 0] = split_lo2(k4.x, k4.y);
        ((__nv_bfloat162*)g_kl)[oq + 1] = split_lo2(k4.z, k4.w);
        sv[r][c * 4 + 0] = v4.x; sv[r][c * 4 + 1] = v4.y;
        sv[r][c * 4 + 2] = v4.z; sv[r][c * 4 + 3] = v4.w;
    }
    __syncthreads();
    // V transpose: 64 d-rows x 4 t-groups = 256 items, exactly one per thread
    {
        int d = tid >> 2, cg = tid & 3;
        size_t ob = (((size_t)bh * HD_ + d) * T_ + t0 + cg * 16) >> 1;  // bf162 units
#pragma unroll
        for (int tt = 0; tt < 16; tt += 2) {
            float v0 = sv[cg * 16 + tt][d], v1 = sv[cg * 16 + tt + 1][d];
            ((__nv_bfloat162*)g_vth)[ob + (tt >> 1)] = split_hi2(v0, v1);
            ((__nv_bfloat162*)g_vtl)[ob + (tt >> 1)] = split_lo2(v0, v1);
        }
    }
}

__global__ void esplit_kernel(const float* __restrict__ rel)
{
    int i = blockIdx.x * blockDim.x + threadIdx.x;   // float4 index
    const int n4 = H_ * T_ * HD_ / 4;
    if (i >= n4) return;
    float4 v = *(const float4*)(rel + (size_t)i * 4);
    ((__nv_bfloat162*)g_eh)[i * 2 + 0] = split_hi2(v.x, v.y);
    ((__nv_bfloat162*)g_eh)[i * 2 + 1] = split_hi2(v.z, v.w);
}

// ---------------------------------------------------------------------------
extern "C" void kernel_launch(void* const* d_in, const int* in_sizes, int n_in,
                              void* d_out, int out_size)
{
    (void)in_sizes; (void)n_in; (void)out_size;
    const float* x      = (const float*)d_in[0];
    const float* W_attn = (const float*)d_in[1];
    const float* b_attn = (const float*)d_in[2];
    const float* W_proj = (const float*)d_in[3];
    const float* b_proj = (const float*)d_in[4];
    const float* rel    = (const float*)d_in[5];
    float* out = (float*)d_out;

    float* qkv = nullptr;
    __nv_bfloat16 *xh, *xl, *yh, *yl, *wah, *wal, *wph, *wpl;
    cudaGetSymbolAddress((void**)&qkv, g_qkv);
    cudaGetSymbolAddress((void**)&xh,  g_xh);
    cudaGetSymbolAddress((void**)&xl,  g_xl);
    cudaGetSymbolAddress((void**)&yh,  g_yh);
    cudaGetSymbolAddress((void**)&yl,  g_yl);
    cudaGetSymbolAddress((void**)&wah, g_wah);
    cudaGetSymbolAddress((void**)&wal, g_wal);
    cudaGetSymbolAddress((void**)&wph, g_wph);
    cudaGetSymbolAddress((void**)&wpl, g_wpl);

    cudaFuncSetAttribute(attn_mma_kernel,
                         cudaFuncAttributeMaxDynamicSharedMemorySize, ATTN_SMEM_BYTES);
    cudaFuncSetAttribute(gemm_mma_kernel,
                         cudaFuncAttributeMaxDynamicSharedMemorySize, GEMM_SMEM_BYTES);

    // prep
    {
        int n4 = B_ * T_ * C_ / 4;
        split_kernel<<<(n4 + 255) / 256, 256>>>(x, xh, xl, n4);
        transpose_split_kernel<<<dim3(C3_ / 32, C_ / 32), dim3(32, 8)>>>(W_attn, wah, wal, C_, C3_);
        transpose_split_kernel<<<dim3(C_ / 32, C_ / 32), dim3(32, 8)>>>(W_proj, wph, wpl, C_, C_);
        int ne4 = H_ * T_ * HD_ / 4;
        esplit_kernel<<<(ne4 + 255) / 256, 256>>>(rel);
    }

    // 1) qkv = x @ W_attn + b_attn
    gemm_mma_kernel<<<dim3(C3_ / 128, (B_ * T_) / 128), 256, GEMM_SMEM_BYTES>>>(
        xh, xl, wah, wal, b_attn, qkv, B_ * T_, C3_, C_);

    // 2) per-head split (+ V transpose)
    qkv_split_kernel<<<dim3(T_ / 64, B_ * H_), 256>>>();

    // 3) MMA flash attention -> yh/yl
    attn_mma_kernel<<<dim3(B_ * H_, T_ / 64), 128, ATTN_SMEM_BYTES>>>();

    // 4) out = y @ W_proj + b_proj
    gemm_mma_kernel<<<dim3(C_ / 128, (B_ * T_) / 128), 256, GEMM_SMEM_BYTES>>>(
        yh, yl, wph, wpl, b_proj, out, B_ * T_, C_, C_);
}

// round 12
// speedup vs baseline: 1.1049x; 1.1049x over previous
#include <cuda_runtime.h>
#include <cuda_bf16.h>
#include <math.h>
#include <cstdint>

#define T_  1024
#define C_  1024
#define H_  16
#define HD_ 64
#define B_  4
#define C3_ 3072

// ---------------- scratch (device globals; allocation-free) ----------------
__device__ float g_qkv[(size_t)B_ * T_ * C3_];

__device__ __nv_bfloat16 g_xh[(size_t)B_ * T_ * C_];
__device__ __nv_bfloat16 g_xl[(size_t)B_ * T_ * C_];
__device__ __nv_bfloat16 g_yh[(size_t)B_ * T_ * C_];
__device__ __nv_bfloat16 g_yl[(size_t)B_ * T_ * C_];
__device__ __nv_bfloat16 g_wah[(size_t)C3_ * C_];
__device__ __nv_bfloat16 g_wal[(size_t)C3_ * C_];
__device__ __nv_bfloat16 g_wph[(size_t)C_ * C_];
__device__ __nv_bfloat16 g_wpl[(size_t)C_ * C_];

// per-head split arrays: [bh][t][d] for q,k ; [bh][d][t] for v ; [h][r][d] for E
__device__ __nv_bfloat16 g_qh[(size_t)B_ * H_ * T_ * HD_];
__device__ __nv_bfloat16 g_ql[(size_t)B_ * H_ * T_ * HD_];
__device__ __nv_bfloat16 g_kh[(size_t)B_ * H_ * T_ * HD_];
__device__ __nv_bfloat16 g_kl[(size_t)B_ * H_ * T_ * HD_];
__device__ __nv_bfloat16 g_vth[(size_t)B_ * H_ * HD_ * T_];
__device__ __nv_bfloat16 g_vtl[(size_t)B_ * H_ * HD_ * T_];
__device__ __nv_bfloat16 g_eh[(size_t)H_ * T_ * HD_];

// ---------------- warp MMA helpers (baseline PTX) ----------------
__device__ __forceinline__ uint32_t smem_u32(const void* p) {
    uint32_t a;
    asm("{ .reg .u64 t; cvta.to.shared.u64 t, %1; cvt.u32.u64 %0, t; }" : "=r"(a) : "l"(p));
    return a;
}
__device__ __forceinline__ void ldsm4(uint32_t* r, uint32_t addr) {
    asm volatile("ldmatrix.sync.aligned.m8n8.x4.shared.b16 {%0,%1,%2,%3}, [%4];"
                 : "=r"(r[0]), "=r"(r[1]), "=r"(r[2]), "=r"(r[3]) : "r"(addr));
}
__device__ __forceinline__ void mma16816(float* c, const uint32_t* a, const uint32_t* b) {
    asm volatile("mma.sync.aligned.m16n8k16.row.col.f32.bf16.bf16.f32 "
                 "{%0,%1,%2,%3}, {%4,%5,%6,%7}, {%8,%9}, {%0,%1,%2,%3};"
                 : "+f"(c[0]), "+f"(c[1]), "+f"(c[2]), "+f"(c[3])
                 : "r"(a[0]), "r"(a[1]), "r"(a[2]), "r"(a[3]), "r"(b[0]), "r"(b[1]));
}
__device__ __forceinline__ __nv_bfloat162 split_hi2(float a, float b) {
    return __nv_bfloat162(__float2bfloat16(a), __float2bfloat16(b));
}
__device__ __forceinline__ __nv_bfloat162 split_lo2(float a, float b) {
    __nv_bfloat16 ha = __float2bfloat16(a), hb = __float2bfloat16(b);
    return __nv_bfloat162(__float2bfloat16(a - __bfloat162float(ha)),
                          __float2bfloat16(b - __bfloat162float(hb)));
}

// ---------------------------------------------------------------------------
// Split-bf16 HMMA GEMM (R7 winner, single-buffered LDG->STS)
// ---------------------------------------------------------------------------
#define PITCH 40
#define TILE_ELEMS (128 * PITCH)

__global__ __launch_bounds__(256, 2)
void gemm_mma_kernel(const __nv_bfloat16* __restrict__ Ah, const __nv_bfloat16* __restrict__ Al,
                     const __nv_bfloat16* __restrict__ Bh, const __nv_bfloat16* __restrict__ Bl,
                     const float* __restrict__ bias, float* __restrict__ out,
                     int M, int N, int K)
{
    __shared__ __nv_bfloat16 smem[4 * TILE_ELEMS];
    const uint32_t sb = smem_u32(smem);
    const uint32_t sAh = sb, sAl = sb + TILE_ELEMS * 2,
                   sBh = sb + 2 * TILE_ELEMS * 2, sBl = sb + 3 * TILE_ELEMS * 2;

    const int tid = threadIdx.x;
    const int wid = tid >> 5, lane = tid & 31;
    const int wr = wid >> 2, wc = wid & 3;
    const int m0 = blockIdx.y * 128, n0g = blockIdx.x * 128;

    float acc[4][4][4];
#pragma unroll
    for (int mt = 0; mt < 4; ++mt)
#pragma unroll
        for (int nt = 0; nt < 4; ++nt)
#pragma unroll
            for (int i = 0; i < 4; ++i) acc[mt][nt][i] = 0.f;

    const int a_row = (lane & 15);
    const int a_col = (lane >> 4) << 3;
    const int b_row = (lane & 7) + ((lane >> 4) << 3);
    const int b_col = (lane & 8);

    const char* gsrc[4] = {
        (const char*)(Ah + (size_t)m0 * K),
        (const char*)(Al + (size_t)m0 * K),
        (const char*)(Bh + (size_t)n0g * K),
        (const char*)(Bl + (size_t)n0g * K) };
    const size_t rowb = (size_t)K * 2;

    const int nch = K / 32;
    for (int ch = 0; ch < nch; ++ch) {
        const size_t kb = (size_t)ch * 64;
#pragma unroll
        for (int t = 0; t < 4; ++t) {
            __nv_bfloat16* dst = smem + t * TILE_ELEMS;
            const char* src = gsrc[t] + kb;
#pragma unroll
            for (int u = 0; u < 2; ++u) {
                int idx = u * 256 + tid;
                int r = idx >> 2, c = idx & 3;
                uint4 v = *(const uint4*)(src + (size_t)r * rowb + c * 16);
                *(uint4*)((char*)(dst + r * PITCH) + c * 16) = v;
            }
        }
        __syncthreads();

#pragma unroll
        for (int ks = 0; ks < 2; ++ks) {
            const int kofs = ks * 16;
            uint32_t Af[4][4], Bf[2][4];
#pragma unroll
            for (int mt = 0; mt < 4; ++mt)
                ldsm4(Af[mt], sAh + ((wr * 64 + mt * 16 + a_row) * PITCH + kofs + a_col) * 2);
#pragma unroll
            for (int nt2 = 0; nt2 < 2; ++nt2)
                ldsm4(Bf[nt2], sBl + ((wc * 32 + nt2 * 16 + b_row) * PITCH + kofs + b_col) * 2);
#pragma unroll
            for (int mt = 0; mt < 4; ++mt)
#pragma unroll
                for (int nt = 0; nt < 4; ++nt)
                    mma16816(acc[mt][nt], Af[mt], &Bf[nt >> 1][(nt & 1) * 2]);

#pragma unroll
            for (int nt2 = 0; nt2 < 2; ++nt2)
                ldsm4(Bf[nt2], sBh + ((wc * 32 + nt2 * 16 + b_row) * PITCH + kofs + b_col) * 2);
#pragma unroll
            for (int mt = 0; mt < 4; ++mt)
#pragma unroll
                for (int nt = 0; nt < 4; ++nt)
                    mma16816(acc[mt][nt], Af[mt], &Bf[nt >> 1][(nt & 1) * 2]);

#pragma unroll
            for (int mt = 0; mt < 4; ++mt)
                ldsm4(Af[mt], sAl + ((wr * 64 + mt * 16 + a_row) * PITCH + kofs + a_col) * 2);
#pragma unroll
            for (int mt = 0; mt < 4; ++mt)
#pragma unroll
                for (int nt = 0; nt < 4; ++nt)
                    mma16816(acc[mt][nt], Af[mt], &Bf[nt >> 1][(nt & 1) * 2]);
        }
        __syncthreads();
    }

    const int qr = lane >> 2, qc = (lane & 3) * 2;
#pragma unroll
    for (int mt = 0; mt < 4; ++mt) {
        const int row = m0 + wr * 64 + mt * 16 + qr;
#pragma unroll
        for (int nt = 0; nt < 4; ++nt) {
            const int col = n0g + wc * 32 + nt * 8 + qc;
            const float b0 = bias[col], b1 = bias[col + 1];
            float2 o0 = {acc[mt][nt][0] + b0, acc[mt][nt][1] + b1};
            float2 o1 = {acc[mt][nt][2] + b0, acc[mt][nt][3] + b1};
            *(float2*)&out[(size_t)row * N + col] = o0;
            *(float2*)&out[(size_t)(row + 8) * N + col] = o1;
        }
    }
}

// ---------------------------------------------------------------------------
// MMA flash attention, i-tile 128 x j-tile 64. 256 threads (8 warps).
// grid (64 bh, 8 i-tiles). S2 stored bf16, aliased with P.
// ---------------------------------------------------------------------------
#define PA 72      // bf16 smem pitch (elements); row = 144 B

#define SQ_H 0          // Q hi: 128*144 = 18432  (E band 192*144=27648 aliases SQ)
#define SQ_L 18432      // Q lo
#define SE   0
#define SK_H 36864      // K hi: 64*144 = 9216
#define SK_L 46080
#define SV_H 55296      // V hi (64 d-rows x 64 t-cols)
#define SV_L 64512
#define SS2  73728      // S2 bf16: 192*144 = 27648 (aliases P region)
#define SP_H 73728      // P hi: 128*144
#define SP_L 92160      // P lo
#define ATTN_SMEM_BYTES 110592

__global__ __launch_bounds__(256, 2)
void attn_mma_kernel()
{
    extern __shared__ char sm[];
    const uint32_t sb = smem_u32(sm);

    const int tid = threadIdx.x, lane = tid & 31, w = tid >> 5;
    const int bh = blockIdx.x, h = bh & 15, b = bh >> 4;
    const int it = 7 - (int)blockIdx.y, i0 = it * 128;   // heavy tiles first

    const int qr = lane >> 2, qc = (lane & 3) * 2;
    const int a_row = lane & 15, a_col = (lane >> 4) << 3;
    const int b_row = (lane & 7) + ((lane >> 4) << 3), b_col = lane & 8;

    // ---- stage Q (hi/lo, 128 rows) and cache Q frags ----
    {
        const char* sqh = (const char*)(g_qh + ((size_t)bh * T_ + i0) * HD_);
        const char* sql = (const char*)(g_ql + ((size_t)bh * T_ + i0) * HD_);
#pragma unroll
        for (int u = 0; u < 4; ++u) {
            int idx = u * 256 + tid;     // 0..1023
            int r = idx >> 3, c = idx & 7;
            *(uint4*)(sm + SQ_H + r * 144 + c * 16) = *(const uint4*)(sqh + r * 128 + c * 16);
            *(uint4*)(sm + SQ_L + r * 144 + c * 16) = *(const uint4*)(sql + r * 128 + c * 16);
        }
    }
    __syncthreads();
    uint32_t Aqh[4][4], Aql[4][4];
#pragma unroll
    for (int ks = 0; ks < 4; ++ks) {
        ldsm4(Aqh[ks], sb + SQ_H + ((w * 16 + a_row) * PA + ks * 16 + a_col) * 2);
        ldsm4(Aql[ks], sb + SQ_L + ((w * 16 + a_row) * PA + ks * 16 + a_col) * 2);
    }

    float o[8][4];
#pragma unroll
    for (int nt = 0; nt < 8; ++nt)
#pragma unroll
        for (int e = 0; e < 4; ++e) o[nt][e] = 0.f;
    float m0r = -1e30f, m1r = -1e30f, l0r = 0.f, l1r = 0.f;

    const int iiA = w * 16 + qr, iiB = iiA + 8;
    const int jtmax = 2 * it + 1;

    for (int jt = 0; jt <= jtmax; ++jt) {
        const int j0 = jt * 64;
        const int dlt = i0 - j0;            // >= -64
        __syncthreads();                    // prev iter's smem reads complete

        // ---- stage K, V (64 rows hi/lo), E band (192 rows) ----
        {
            const char* kh = (const char*)(g_kh + ((size_t)bh * T_ + j0) * HD_);
            const char* kl = (const char*)(g_kl + ((size_t)bh * T_ + j0) * HD_);
#pragma unroll
            for (int u = 0; u < 2; ++u) {
                int idx = u * 256 + tid;    // 0..511
                int r = idx >> 3, c = idx & 7;
                *(uint4*)(sm + SK_H + r * 144 + c * 16) = *(const uint4*)(kh + r * 128 + c * 16);
                *(uint4*)(sm + SK_L + r * 144 + c * 16) = *(const uint4*)(kl + r * 128 + c * 16);
            }
            const char* vh = (const char*)(g_vth + (size_t)bh * HD_ * T_ + j0);
            const char* vl = (const char*)(g_vtl + (size_t)bh * HD_ * T_ + j0);
#pragma unroll
            for (int u = 0; u < 2; ++u) {
                int idx = u * 256 + tid;
                int r = idx >> 3, c = idx & 7;
                *(uint4*)(sm + SV_H + r * 144 + c * 16) = *(const uint4*)(vh + (size_t)r * (T_ * 2) + c * 16);
                *(uint4*)(sm + SV_L + r * 144 + c * 16) = *(const uint4*)(vl + (size_t)r * (T_ * 2) + c * 16);
            }
            const char* ep = (const char*)(g_eh + (size_t)h * T_ * HD_);
#pragma unroll
            for (int u = 0; u < 6; ++u) {
                int idx = u * 256 + tid;    // 0..1535
                int r = idx >> 3, c = idx & 7;   // r 0..191
                int er = dlt - 63 + r;
                er = min(max(er, 0), T_ - 1);
                *(uint4*)(sm + SE + r * 144 + c * 16) = *(const uint4*)(ep + (size_t)er * 128 + c * 16);
            }
        }
        __syncthreads();

        // ---- phase A: S2 = E_band(192x64) @ K^T -> smem (bf16), 12 m16 tiles ----
#pragma unroll
        for (int g = 0; g < 2; ++g) {
            const int tile = g * 8 + w;
            if (tile < 12) {
                float s2a[8][4];
#pragma unroll
                for (int nt = 0; nt < 8; ++nt)
#pragma unroll
                    for (int e = 0; e < 4; ++e) s2a[nt][e] = 0.f;
#pragma unroll
                for (int ks = 0; ks < 4; ++ks) {
                    uint32_t Ea[4], Kb[4][4];
                    ldsm4(Ea, sb + SE + ((tile * 16 + a_row) * PA + ks * 16 + a_col) * 2);
#pragma unroll
                    for (int nt2 = 0; nt2 < 4; ++nt2)
                        ldsm4(Kb[nt2], sb + SK_H + ((nt2 * 16 + b_row) * PA + ks * 16 + b_col) * 2);
#pragma unroll
                    for (int nt = 0; nt < 8; ++nt)
                        mma16816(s2a[nt], Ea, &Kb[nt >> 1][(nt & 1) * 2]);
                }
                const int r0 = tile * 16 + qr;
#pragma unroll
                for (int nt = 0; nt < 8; ++nt) {
                    const int col = nt * 8 + qc;
                    *(__nv_bfloat162*)(sm + SS2 + (r0 * PA + col) * 2) = split_hi2(s2a[nt][0], s2a[nt][1]);
                    *(__nv_bfloat162*)(sm + SS2 + ((r0 + 8) * PA + col) * 2) = split_hi2(s2a[nt][2], s2a[nt][3]);
                }
            }
        }

        // ---- phase B: S1 = Q @ K^T (3-term split) ----
        float p[8][4];
#pragma unroll
        for (int nt = 0; nt < 8; ++nt)
#pragma unroll
            for (int e = 0; e < 4; ++e) p[nt][e] = 0.f;
#pragma unroll
        for (int ks = 0; ks < 4; ++ks) {
            uint32_t Kbh[4][4], Kbl[4][4];
#pragma unroll
            for (int nt2 = 0; nt2 < 4; ++nt2) {
                ldsm4(Kbh[nt2], sb + SK_H + ((nt2 * 16 + b_row) * PA + ks * 16 + b_col) * 2);
                ldsm4(Kbl[nt2], sb + SK_L + ((nt2 * 16 + b_row) * PA + ks * 16 + b_col) * 2);
            }
#pragma unroll
            for (int nt = 0; nt < 8; ++nt) {
                mma16816(p[nt], Aqh[ks], &Kbh[nt >> 1][(nt & 1) * 2]);
                mma16816(p[nt], Aqh[ks], &Kbl[nt >> 1][(nt & 1) * 2]);
                mma16816(p[nt], Aql[ks], &Kbh[nt >> 1][(nt & 1) * 2]);
            }
        }
        __syncthreads();   // S2 visible to all warps

        // ---- softmax: gather S2 (bf16), scale, mask, online update ----
        const bool maskt = (dlt < 64);
        float mx0 = -1e30f, mx1 = -1e30f;
#pragma unroll
        for (int nt = 0; nt < 8; ++nt) {
            const int jj0 = nt * 8 + qc;
            float s2v0 = __bfloat162float(*(const __nv_bfloat16*)(sm + SS2 + ((63 + iiA - jj0) * PA + jj0) * 2));
            float s2v1 = __bfloat162float(*(const __nv_bfloat16*)(sm + SS2 + ((62 + iiA - jj0) * PA + jj0 + 1) * 2));
            float s2v2 = __bfloat162float(*(const __nv_bfloat16*)(sm + SS2 + ((63 + iiB - jj0) * PA + jj0) * 2));
            float s2v3 = __bfloat162float(*(const __nv_bfloat16*)(sm + SS2 + ((62 + iiB - jj0) * PA + jj0 + 1) * 2));
            float v0 = (p[nt][0] + s2v0) * 0.125f;
            float v1 = (p[nt][1] + s2v1) * 0.125f;
            float v2 = (p[nt][2] + s2v2) * 0.125f;
            float v3 = (p[nt][3] + s2v3) * 0.125f;
            if (maskt) {
                if (jj0 > iiA + dlt) v0 = -1e30f;
                if (jj0 + 1 > iiA + dlt) v1 = -1e30f;
                if (jj0 > iiB + dlt) v2 = -1e30f;
                if (jj0 + 1 > iiB + dlt) v3 = -1e30f;
            }
            p[nt][0] = v0; p[nt][1] = v1; p[nt][2] = v2; p[nt][3] = v3;
            mx0 = fmaxf(mx0, fmaxf(v0, v1));
            mx1 = fmaxf(mx1, fmaxf(v2, v3));
        }
        mx0 = fmaxf(mx0, __shfl_xor_sync(0xffffffffu, mx0, 1));
        mx0 = fmaxf(mx0, __shfl_xor_sync(0xffffffffu, mx0, 2));
        mx1 = fmaxf(mx1, __shfl_xor_sync(0xffffffffu, mx1, 1));
        mx1 = fmaxf(mx1, __shfl_xor_sync(0xffffffffu, mx1, 2));
        const float mn0 = fmaxf(m0r, mx0), mn1 = fmaxf(m1r, mx1);
        const float c0 = __expf(m0r - mn0), c1 = __expf(m1r - mn1);
        float s0 = 0.f, s1s = 0.f;
#pragma unroll
        for (int nt = 0; nt < 8; ++nt) {
            p[nt][0] = __expf(p[nt][0] - mn0);
            p[nt][1] = __expf(p[nt][1] - mn0);
            p[nt][2] = __expf(p[nt][2] - mn1);
            p[nt][3] = __expf(p[nt][3] - mn1);
            s0 += p[nt][0] + p[nt][1];
            s1s += p[nt][2] + p[nt][3];
        }
        s0 += __shfl_xor_sync(0xffffffffu, s0, 1);
        s0 += __shfl_xor_sync(0xffffffffu, s0, 2);
        s1s += __shfl_xor_sync(0xffffffffu, s1s, 1);
        s1s += __shfl_xor_sync(0xffffffffu, s1s, 2);
        l0r = l0r * c0 + s0;
        l1r = l1r * c1 + s1s;
        m0r = mn0; m1r = mn1;
#pragma unroll
        for (int nt = 0; nt < 8; ++nt) {
            o[nt][0] *= c0; o[nt][1] *= c0;
            o[nt][2] *= c1; o[nt][3] *= c1;
        }
        __syncthreads();   // all S2 reads done before P overwrites the region

        // ---- write P (hi/lo bf16) ----
#pragma unroll
        for (int nt = 0; nt < 8; ++nt) {
            const int col = nt * 8 + qc;
            *(__nv_bfloat162*)(sm + SP_H + (iiA * PA + col) * 2) = split_hi2(p[nt][0], p[nt][1]);
            *(__nv_bfloat162*)(sm + SP_L + (iiA * PA + col) * 2) = split_lo2(p[nt][0], p[nt][1]);
            *(__nv_bfloat162*)(sm + SP_H + (iiB * PA + col) * 2) = split_hi2(p[nt][2], p[nt][3]);
            *(__nv_bfloat162*)(sm + SP_L + (iiB * PA + col) * 2) = split_lo2(p[nt][2], p[nt][3]);
        }
        __syncthreads();   // P visible

        // ---- PV: O += P @ V (3-term) ----
#pragma unroll
        for (int ks = 0; ks < 4; ++ks) {
            uint32_t Ap[4], Apl[4], Vb[4][4], Vbl[4][4];
            ldsm4(Ap,  sb + SP_H + ((w * 16 + a_row) * PA + ks * 16 + a_col) * 2);
            ldsm4(Apl, sb + SP_L + ((w * 16 + a_row) * PA + ks * 16 + a_col) * 2);
#pragma unroll
            for (int nt2 = 0; nt2 < 4; ++nt2) {
                ldsm4(Vb[nt2],  sb + SV_H + ((nt2 * 16 + b_row) * PA + ks * 16 + b_col) * 2);
                ldsm4(Vbl[nt2], sb + SV_L + ((nt2 * 16 + b_row) * PA + ks * 16 + b_col) * 2);
            }
#pragma unroll
            for (int nt = 0; nt < 8; ++nt) {
                mma16816(o[nt], Ap,  &Vb[nt >> 1][(nt & 1) * 2]);
                mma16816(o[nt], Ap,  &Vbl[nt >> 1][(nt & 1) * 2]);
                mma16816(o[nt], Apl, &Vb[nt >> 1][(nt & 1) * 2]);
            }
        }
    }

    // ---- write y (split bf16 directly) ----
    const float iv0 = 1.f / l0r, iv1 = 1.f / l1r;
    const size_t rowA = (size_t)b * T_ + i0 + iiA;
    const size_t rowB = rowA + 8;
#pragma unroll
    for (int nt = 0; nt < 8; ++nt) {
        const int col = h * HD_ + nt * 8 + qc;
        float v0 = o[nt][0] * iv0, v1 = o[nt][1] * iv0;
        float v2 = o[nt][2] * iv1, v3 = o[nt][3] * iv1;
        ((__nv_bfloat162*)g_yh)[(rowA * C_ + col) >> 1] = split_hi2(v0, v1);
        ((__nv_bfloat162*)g_yl)[(rowA * C_ + col) >> 1] = split_lo2(v0, v1);
        ((__nv_bfloat162*)g_yh)[(rowB * C_ + col) >> 1] = split_hi2(v2, v3);
        ((__nv_bfloat162*)g_yl)[(rowB * C_ + col) >> 1] = split_lo2(v2, v3);
    }
}

// ---------------------------------------------------------------------------
// Prep kernels
// ---------------------------------------------------------------------------
__global__ void split_kernel(const float* __restrict__ src,
                             __nv_bfloat16* __restrict__ hi,
                             __nv_bfloat16* __restrict__ lo, int n4)
{
    int i = blockIdx.x * blockDim.x + threadIdx.x;
    if (i >= n4) return;
    float4 v = *(const float4*)(src + (size_t)i * 4);
    ((__nv_bfloat162*)hi)[i * 2 + 0] = split_hi2(v.x, v.y);
    ((__nv_bfloat162*)hi)[i * 2 + 1] = split_hi2(v.z, v.w);
    ((__nv_bfloat162*)lo)[i * 2 + 0] = split_lo2(v.x, v.y);
    ((__nv_bfloat162*)lo)[i * 2 + 1] = split_lo2(v.z, v.w);
}

__global__ void transpose_split_kernel(const float* __restrict__ W,
                                       __nv_bfloat16* __restrict__ th,
                                       __nv_bfloat16* __restrict__ tl, int K, int N)
{
    __shared__ float tile[32][33];
    const int tx = threadIdx.x, ty = threadIdx.y;
    const int n0 = blockIdx.x * 32, k0 = blockIdx.y * 32;
#pragma unroll
    for (int j = 0; j < 4; ++j)
        tile[ty + j * 8][tx] = W[(size_t)(k0 + ty + j * 8) * N + n0 + tx];
    __syncthreads();
#pragma unroll
    for (int j = 0; j < 4; ++j) {
        float v = tile[tx][ty + j * 8];
        __nv_bfloat16 hh = __float2bfloat16(v);
        __nv_bfloat16 ll = __float2bfloat16(v - __bfloat162float(hh));
        size_t o = (size_t)(n0 + ty + j * 8) * K + k0 + tx;
        th[o] = hh; tl[o] = ll;
    }
}

// split qkv into per-head q/k (row) and v (transposed) bf16 hi/lo
__global__ __launch_bounds__(256)
void qkv_split_kernel()
{
    __shared__ float sv[64][65];
    const int tid = threadIdx.x;
    const int bh = blockIdx.y, t0 = blockIdx.x * 64;
    const int b = bh >> 4, h = bh & 15;
    const float* src = g_qkv + ((size_t)(b * T_ + t0)) * C3_ + h * HD_;

#pragma unroll
    for (int u = 0; u < 4; ++u) {
        int idx = u * 256 + tid;
        int r = idx >> 4, c = idx & 15;      // c in float4 units
        float4 q4 = *(const float4*)(src + (size_t)r * C3_ + c * 4);
        float4 k4 = *(const float4*)(src + (size_t)r * C3_ + C_ + c * 4);
        float4 v4 = *(const float4*)(src + (size_t)r * C3_ + 2 * C_ + c * 4);
        size_t oq = (((size_t)bh * T_ + t0 + r) * HD_ + c * 4) >> 1;  // bf162 units
        ((__nv_bfloat162*)g_qh)[oq + 0] = split_hi2(q4.x, q4.y);
        ((__nv_bfloat162*)g_qh)[oq + 1] = split_hi2(q4.z, q4.w);
        ((__nv_bfloat162*)g_ql)[oq + 0] = split_lo2(q4.x, q4.y);
        ((__nv_bfloat162*)g_ql)[oq + 1] = split_lo2(q4.z, q4.w);
        ((__nv_bfloat162*)g_kh)[oq + 0] = split_hi2(k4.x, k4.y);
        ((__nv_bfloat162*)g_kh)[oq + 1] = split_hi2(k4.z, k4.w);
        ((__nv_bfloat162*)g_kl)[oq + 0] = split_lo2(k4.x, k4.y);
        ((__nv_bfloat162*)g_kl)[oq + 1] = split_lo2(k4.z, k4.w);
        sv[r][c * 4 + 0] = v4.x; sv[r][c * 4 + 1] = v4.y;
        sv[r][c * 4 + 2] = v4.z; sv[r][c * 4 + 3] = v4.w;
    }
    __syncthreads();
    // V transpose: 64 d-rows x 4 t-groups = 256 items, exactly one per thread
    {
        int d = tid >> 2, cg = tid & 3;
        size_t ob = (((size_t)bh * HD_ + d) * T_ + t0 + cg * 16) >> 1;  // bf162 units
#pragma unroll
        for (int tt = 0; tt < 16; tt += 2) {
            float v0 = sv[cg * 16 + tt][d], v1 = sv[cg * 16 + tt + 1][d];
            ((__nv_bfloat162*)g_vth)[ob + (tt >> 1)] = split_hi2(v0, v1);
            ((__nv_bfloat162*)g_vtl)[ob + (tt >> 1)] = split_lo2(v0, v1);
        }
    }
}

__global__ void esplit_kernel(const float* __restrict__ rel)
{
    int i = blockIdx.x * blockDim.x + threadIdx.x;   // float4 index
    const int n4 = H_ * T_ * HD_ / 4;
    if (i >= n4) return;
    float4 v = *(const float4*)(rel + (size_t)i * 4);
    ((__nv_bfloat162*)g_eh)[i * 2 + 0] = split_hi2(v.x, v.y);
    ((__nv_bfloat162*)g_eh)[i * 2 + 1] = split_hi2(v.z, v.w);
}

// ---------------------------------------------------------------------------
extern "C" void kernel_launch(void* const* d_in, const int* in_sizes, int n_in,
                              void* d_out, int out_size)
{
    (void)in_sizes; (void)n_in; (void)out_size;
    const float* x      = (const float*)d_in[0];
    const float* W_attn = (const float*)d_in[1];
    const float* b_attn = (const float*)d_in[2];
    const float* W_proj = (const float*)d_in[3];
    const float* b_proj = (const float*)d_in[4];
    const float* rel    = (const float*)d_in[5];
    float* out = (float*)d_out;

    float* qkv = nullptr;
    __nv_bfloat16 *xh, *xl, *yh, *yl, *wah, *wal, *wph, *wpl;
    cudaGetSymbolAddress((void**)&qkv, g_qkv);
    cudaGetSymbolAddress((void**)&xh,  g_xh);
    cudaGetSymbolAddress((void**)&xl,  g_xl);
    cudaGetSymbolAddress((void**)&yh,  g_yh);
    cudaGetSymbolAddress((void**)&yl,  g_yl);
    cudaGetSymbolAddress((void**)&wah, g_wah);
    cudaGetSymbolAddress((void**)&wal, g_wal);
    cudaGetSymbolAddress((void**)&wph, g_wph);
    cudaGetSymbolAddress((void**)&wpl, g_wpl);

    cudaFuncSetAttribute(attn_mma_kernel,
                         cudaFuncAttributeMaxDynamicSharedMemorySize, ATTN_SMEM_BYTES);

    // prep
    {
        int n4 = B_ * T_ * C_ / 4;
        split_kernel<<<(n4 + 255) / 256, 256>>>(x, xh, xl, n4);
        transpose_split_kernel<<<dim3(C3_ / 32, C_ / 32), dim3(32, 8)>>>(W_attn, wah, wal, C_, C3_);
        transpose_split_kernel<<<dim3(C_ / 32, C_ / 32), dim3(32, 8)>>>(W_proj, wph, wpl, C_, C_);
        int ne4 = H_ * T_ * HD_ / 4;
        esplit_kernel<<<(ne4 + 255) / 256, 256>>>(rel);
    }

    // 1) qkv = x @ W_attn + b_attn
    gemm_mma_kernel<<<dim3(C3_ / 128, (B_ * T_) / 128), 256>>>(
        xh, xl, wah, wal, b_attn, qkv, B_ * T_, C3_, C_);

    // 2) per-head split (+ V transpose)
    qkv_split_kernel<<<dim3(T_ / 64, B_ * H_), 256>>>();

    // 3) MMA flash attention (i-tile 128) -> yh/yl
    attn_mma_kernel<<<dim3(B_ * H_, T_ / 128), 256, ATTN_SMEM_BYTES>>>();

    // 4) out = y @ W_proj + b_proj
    gemm_mma_kernel<<<dim3(C_ / 128, (B_ * T_) / 128), 256>>>(
        yh, yl, wph, wpl, b_proj, out, B_ * T_, C_, C_);
}

// round 13
// speedup vs baseline: 1.1750x; 1.0635x over previous
#include <cuda_runtime.h>
#include <cuda_bf16.h>
#include <math.h>
#include <cstdint>

#define T_  1024
#define C_  1024
#define H_  16
#define HD_ 64
#define B_  4
#define C3_ 3072

// ---------------- scratch (device globals; allocation-free) ----------------
__device__ float g_qkv[(size_t)B_ * T_ * C3_];

__device__ __nv_bfloat16 g_xh[(size_t)B_ * T_ * C_];
__device__ __nv_bfloat16 g_xl[(size_t)B_ * T_ * C_];
__device__ __nv_bfloat16 g_yh[(size_t)B_ * T_ * C_];
__device__ __nv_bfloat16 g_yl[(size_t)B_ * T_ * C_];
__device__ __nv_bfloat16 g_wah[(size_t)C3_ * C_];
__device__ __nv_bfloat16 g_wal[(size_t)C3_ * C_];
__device__ __nv_bfloat16 g_wph[(size_t)C_ * C_];
__device__ __nv_bfloat16 g_wpl[(size_t)C_ * C_];

// per-head split arrays: [bh][t][d] for q,k ; [bh][d][t] for v ; [h][r][d] for E
__device__ __nv_bfloat16 g_qh[(size_t)B_ * H_ * T_ * HD_];
__device__ __nv_bfloat16 g_ql[(size_t)B_ * H_ * T_ * HD_];
__device__ __nv_bfloat16 g_kh[(size_t)B_ * H_ * T_ * HD_];
__device__ __nv_bfloat16 g_kl[(size_t)B_ * H_ * T_ * HD_];
__device__ __nv_bfloat16 g_vth[(size_t)B_ * H_ * HD_ * T_];
__device__ __nv_bfloat16 g_vtl[(size_t)B_ * H_ * HD_ * T_];
__device__ __nv_bfloat16 g_eh[(size_t)H_ * T_ * HD_];

// ---------------- warp MMA helpers (baseline PTX) ----------------
__device__ __forceinline__ uint32_t smem_u32(const void* p) {
    uint32_t a;
    asm("{ .reg .u64 t; cvta.to.shared.u64 t, %1; cvt.u32.u64 %0, t; }" : "=r"(a) : "l"(p));
    return a;
}
__device__ __forceinline__ void ldsm4(uint32_t* r, uint32_t addr) {
    asm volatile("ldmatrix.sync.aligned.m8n8.x4.shared.b16 {%0,%1,%2,%3}, [%4];"
                 : "=r"(r[0]), "=r"(r[1]), "=r"(r[2]), "=r"(r[3]) : "r"(addr));
}
__device__ __forceinline__ void mma16816(float* c, const uint32_t* a, const uint32_t* b) {
    asm volatile("mma.sync.aligned.m16n8k16.row.col.f32.bf16.bf16.f32 "
                 "{%0,%1,%2,%3}, {%4,%5,%6,%7}, {%8,%9}, {%0,%1,%2,%3};"
                 : "+f"(c[0]), "+f"(c[1]), "+f"(c[2]), "+f"(c[3])
                 : "r"(a[0]), "r"(a[1]), "r"(a[2]), "r"(a[3]), "r"(b[0]), "r"(b[1]));
}
__device__ __forceinline__ __nv_bfloat162 split_hi2(float a, float b) {
    return __nv_bfloat162(__float2bfloat16(a), __float2bfloat16(b));
}
__device__ __forceinline__ __nv_bfloat162 split_lo2(float a, float b) {
    __nv_bfloat16 ha = __float2bfloat16(a), hb = __float2bfloat16(b);
    return __nv_bfloat162(__float2bfloat16(a - __bfloat162float(ha)),
                          __float2bfloat16(b - __bfloat162float(hb)));
}

// ---------------------------------------------------------------------------
// Split-bf16 HMMA GEMM. Tile 128x128, K-chunk 64, pitch 72 (conflict-free
// ldmatrix). Single-buffered. 8 warps (2x4), warp tile 64x32.
// ---------------------------------------------------------------------------
#define GP 72                       // bf16 pitch; row = 144 B
#define GT_BYTES (128 * GP * 2)     // 18432 per tile
#define GEMM_SMEM_BYTES (4 * GT_BYTES)   // 73728

__global__ __launch_bounds__(256, 2)
void gemm_mma_kernel(const __nv_bfloat16* __restrict__ Ah, const __nv_bfloat16* __restrict__ Al,
                     const __nv_bfloat16* __restrict__ Bh, const __nv_bfloat16* __restrict__ Bl,
                     const float* __restrict__ bias, float* __restrict__ out,
                     int M, int N, int K)
{
    extern __shared__ char gsm[];
    const uint32_t sb = smem_u32(gsm);
    const uint32_t sAh = sb, sAl = sb + GT_BYTES,
                   sBh = sb + 2 * GT_BYTES, sBl = sb + 3 * GT_BYTES;

    const int tid = threadIdx.x;
    const int wid = tid >> 5, lane = tid & 31;
    const int wr = wid >> 2, wc = wid & 3;
    const int m0 = blockIdx.y * 128, n0g = blockIdx.x * 128;

    float acc[4][4][4];
#pragma unroll
    for (int mt = 0; mt < 4; ++mt)
#pragma unroll
        for (int nt = 0; nt < 4; ++nt)
#pragma unroll
            for (int i = 0; i < 4; ++i) acc[mt][nt][i] = 0.f;

    const int a_row = (lane & 15);
    const int a_col = (lane >> 4) << 3;
    const int b_row = (lane & 7) + ((lane >> 4) << 3);
    const int b_col = (lane & 8);

    const char* gsrc[4] = {
        (const char*)(Ah + (size_t)m0 * K),
        (const char*)(Al + (size_t)m0 * K),
        (const char*)(Bh + (size_t)n0g * K),
        (const char*)(Bl + (size_t)n0g * K) };
    const size_t rowb = (size_t)K * 2;

    const int nch = K / 64;
    for (int ch = 0; ch < nch; ++ch) {
        const size_t kb = (size_t)ch * 128;   // 64 bf16 = 128 B
        // stage 4 tiles: 128 rows x 64 bf16 (128 B) each, pitch 144 B
#pragma unroll
        for (int t = 0; t < 4; ++t) {
            char* dst = gsm + t * GT_BYTES;
            const char* src = gsrc[t] + kb;
#pragma unroll
            for (int u = 0; u < 4; ++u) {
                int idx = u * 256 + tid;          // 0..1023
                int r = idx >> 3, c = idx & 7;    // 8 x 16B per row
                uint4 v = *(const uint4*)(src + (size_t)r * rowb + c * 16);
                *(uint4*)(dst + r * 144 + c * 16) = v;
            }
        }
        __syncthreads();

#pragma unroll
        for (int ks = 0; ks < 4; ++ks) {
            const int kofs = ks * 16;
            uint32_t Af[4][4], Bf[2][4];
#pragma unroll
            for (int mt = 0; mt < 4; ++mt)
                ldsm4(Af[mt], sAh + ((wr * 64 + mt * 16 + a_row) * GP + kofs + a_col) * 2);
#pragma unroll
            for (int nt2 = 0; nt2 < 2; ++nt2)
                ldsm4(Bf[nt2], sBl + ((wc * 32 + nt2 * 16 + b_row) * GP + kofs + b_col) * 2);
#pragma unroll
            for (int mt = 0; mt < 4; ++mt)
#pragma unroll
                for (int nt = 0; nt < 4; ++nt)
                    mma16816(acc[mt][nt], Af[mt], &Bf[nt >> 1][(nt & 1) * 2]);

#pragma unroll
            for (int nt2 = 0; nt2 < 2; ++nt2)
                ldsm4(Bf[nt2], sBh + ((wc * 32 + nt2 * 16 + b_row) * GP + kofs + b_col) * 2);
#pragma unroll
            for (int mt = 0; mt < 4; ++mt)
#pragma unroll
                for (int nt = 0; nt < 4; ++nt)
                    mma16816(acc[mt][nt], Af[mt], &Bf[nt >> 1][(nt & 1) * 2]);

#pragma unroll
            for (int mt = 0; mt < 4; ++mt)
                ldsm4(Af[mt], sAl + ((wr * 64 + mt * 16 + a_row) * GP + kofs + a_col) * 2);
#pragma unroll
            for (int mt = 0; mt < 4; ++mt)
#pragma unroll
                for (int nt = 0; nt < 4; ++nt)
                    mma16816(acc[mt][nt], Af[mt], &Bf[nt >> 1][(nt & 1) * 2]);
        }
        __syncthreads();
    }

    const int qr = lane >> 2, qc = (lane & 3) * 2;
#pragma unroll
    for (int mt = 0; mt < 4; ++mt) {
        const int row = m0 + wr * 64 + mt * 16 + qr;
#pragma unroll
        for (int nt = 0; nt < 4; ++nt) {
            const int col = n0g + wc * 32 + nt * 8 + qc;
            const float b0 = bias[col], b1 = bias[col + 1];
            float2 o0 = {acc[mt][nt][0] + b0, acc[mt][nt][1] + b1};
            float2 o1 = {acc[mt][nt][2] + b0, acc[mt][nt][3] + b1};
            *(float2*)&out[(size_t)row * N + col] = o0;
            *(float2*)&out[(size_t)(row + 8) * N + col] = o1;
        }
    }
}

// ---------------------------------------------------------------------------
// MMA flash attention, i-tile 128 x j-tile 64 (R12 winner, unchanged).
// ---------------------------------------------------------------------------
#define PA 72      // bf16 smem pitch (elements); row = 144 B

#define SQ_H 0          // Q hi: 128*144 = 18432  (E band 192*144=27648 aliases SQ)
#define SQ_L 18432      // Q lo
#define SE   0
#define SK_H 36864      // K hi: 64*144 = 9216
#define SK_L 46080
#define SV_H 55296      // V hi (64 d-rows x 64 t-cols)
#define SV_L 64512
#define SS2  73728      // S2 bf16: 192*144 = 27648 (aliases P region)
#define SP_H 73728      // P hi: 128*144
#define SP_L 92160      // P lo
#define ATTN_SMEM_BYTES 110592

__global__ __launch_bounds__(256, 2)
void attn_mma_kernel()
{
    extern __shared__ char sm[];
    const uint32_t sb = smem_u32(sm);

    const int tid = threadIdx.x, lane = tid & 31, w = tid >> 5;
    const int bh = blockIdx.x, h = bh & 15, b = bh >> 4;
    const int it = 7 - (int)blockIdx.y, i0 = it * 128;   // heavy tiles first

    const int qr = lane >> 2, qc = (lane & 3) * 2;
    const int a_row = lane & 15, a_col = (lane >> 4) << 3;
    const int b_row = (lane & 7) + ((lane >> 4) << 3), b_col = lane & 8;

    // ---- stage Q (hi/lo, 128 rows) and cache Q frags ----
    {
        const char* sqh = (const char*)(g_qh + ((size_t)bh * T_ + i0) * HD_);
        const char* sql = (const char*)(g_ql + ((size_t)bh * T_ + i0) * HD_);
#pragma unroll
        for (int u = 0; u < 4; ++u) {
            int idx = u * 256 + tid;     // 0..1023
            int r = idx >> 3, c = idx & 7;
            *(uint4*)(sm + SQ_H + r * 144 + c * 16) = *(const uint4*)(sqh + r * 128 + c * 16);
            *(uint4*)(sm + SQ_L + r * 144 + c * 16) = *(const uint4*)(sql + r * 128 + c * 16);
        }
    }
    __syncthreads();
    uint32_t Aqh[4][4], Aql[4][4];
#pragma unroll
    for (int ks = 0; ks < 4; ++ks) {
        ldsm4(Aqh[ks], sb + SQ_H + ((w * 16 + a_row) * PA + ks * 16 + a_col) * 2);
        ldsm4(Aql[ks], sb + SQ_L + ((w * 16 + a_row) * PA + ks * 16 + a_col) * 2);
    }

    float o[8][4];
#pragma unroll
    for (int nt = 0; nt < 8; ++nt)
#pragma unroll
        for (int e = 0; e < 4; ++e) o[nt][e] = 0.f;
    float m0r = -1e30f, m1r = -1e30f, l0r = 0.f, l1r = 0.f;

    const int iiA = w * 16 + qr, iiB = iiA + 8;
    const int jtmax = 2 * it + 1;

    for (int jt = 0; jt <= jtmax; ++jt) {
        const int j0 = jt * 64;
        const int dlt = i0 - j0;            // >= -64
        __syncthreads();                    // prev iter's smem reads complete

        // ---- stage K, V (64 rows hi/lo), E band (192 rows) ----
        {
            const char* kh = (const char*)(g_kh + ((size_t)bh * T_ + j0) * HD_);
            const char* kl = (const char*)(g_kl + ((size_t)bh * T_ + j0) * HD_);
#pragma unroll
            for (int u = 0; u < 2; ++u) {
                int idx = u * 256 + tid;    // 0..511
                int r = idx >> 3, c = idx & 7;
                *(uint4*)(sm + SK_H + r * 144 + c * 16) = *(const uint4*)(kh + r * 128 + c * 16);
                *(uint4*)(sm + SK_L + r * 144 + c * 16) = *(const uint4*)(kl + r * 128 + c * 16);
            }
            const char* vh = (const char*)(g_vth + (size_t)bh * HD_ * T_ + j0);
            const char* vl = (const char*)(g_vtl + (size_t)bh * HD_ * T_ + j0);
#pragma unroll
            for (int u = 0; u < 2; ++u) {
                int idx = u * 256 + tid;
                int r = idx >> 3, c = idx & 7;
                *(uint4*)(sm + SV_H + r * 144 + c * 16) = *(const uint4*)(vh + (size_t)r * (T_ * 2) + c * 16);
                *(uint4*)(sm + SV_L + r * 144 + c * 16) = *(const uint4*)(vl + (size_t)r * (T_ * 2) + c * 16);
            }
            const char* ep = (const char*)(g_eh + (size_t)h * T_ * HD_);
#pragma unroll
            for (int u = 0; u < 6; ++u) {
                int idx = u * 256 + tid;    // 0..1535
                int r = idx >> 3, c = idx & 7;   // r 0..191
                int er = dlt - 63 + r;
                er = min(max(er, 0), T_ - 1);
                *(uint4*)(sm + SE + r * 144 + c * 16) = *(const uint4*)(ep + (size_t)er * 128 + c * 16);
            }
        }
        __syncthreads();

        // ---- phase A: S2 = E_band(192x64) @ K^T -> smem (bf16), 12 m16 tiles ----
#pragma unroll
        for (int g = 0; g < 2; ++g) {
            const int tile = g * 8 + w;
            if (tile < 12) {
                float s2a[8][4];
#pragma unroll
                for (int nt = 0; nt < 8; ++nt)
#pragma unroll
                    for (int e = 0; e < 4; ++e) s2a[nt][e] = 0.f;
#pragma unroll
                for (int ks = 0; ks < 4; ++ks) {
                    uint32_t Ea[4], Kb[4][4];
                    ldsm4(Ea, sb + SE + ((tile * 16 + a_row) * PA + ks * 16 + a_col) * 2);
#pragma unroll
                    for (int nt2 = 0; nt2 < 4; ++nt2)
                        ldsm4(Kb[nt2], sb + SK_H + ((nt2 * 16 + b_row) * PA + ks * 16 + b_col) * 2);
#pragma unroll
                    for (int nt = 0; nt < 8; ++nt)
                        mma16816(s2a[nt], Ea, &Kb[nt >> 1][(nt & 1) * 2]);
                }
                const int r0 = tile * 16 + qr;
#pragma unroll
                for (int nt = 0; nt < 8; ++nt) {
                    const int col = nt * 8 + qc;
                    *(__nv_bfloat162*)(sm + SS2 + (r0 * PA + col) * 2) = split_hi2(s2a[nt][0], s2a[nt][1]);
                    *(__nv_bfloat162*)(sm + SS2 + ((r0 + 8) * PA + col) * 2) = split_hi2(s2a[nt][2], s2a[nt][3]);
                }
            }
        }

        // ---- phase B: S1 = Q @ K^T (3-term split) ----
        float p[8][4];
#pragma unroll
        for (int nt = 0; nt < 8; ++nt)
#pragma unroll
            for (int e = 0; e < 4; ++e) p[nt][e] = 0.f;
#pragma unroll
        for (int ks = 0; ks < 4; ++ks) {
            uint32_t Kbh[4][4], Kbl[4][4];
#pragma unroll
            for (int nt2 = 0; nt2 < 4; ++nt2) {
                ldsm4(Kbh[nt2], sb + SK_H + ((nt2 * 16 + b_row) * PA + ks * 16 + b_col) * 2);
                ldsm4(Kbl[nt2], sb + SK_L + ((nt2 * 16 + b_row) * PA + ks * 16 + b_col) * 2);
            }
#pragma unroll
            for (int nt = 0; nt < 8; ++nt) {
                mma16816(p[nt], Aqh[ks], &Kbh[nt >> 1][(nt & 1) * 2]);
                mma16816(p[nt], Aqh[ks], &Kbl[nt >> 1][(nt & 1) * 2]);
                mma16816(p[nt], Aql[ks], &Kbh[nt >> 1][(nt & 1) * 2]);
            }
        }
        __syncthreads();   // S2 visible to all warps

        // ---- softmax: gather S2 (bf16), scale, mask, online update ----
        const bool maskt = (dlt < 64);
        float mx0 = -1e30f, mx1 = -1e30f;
#pragma unroll
        for (int nt = 0; nt < 8; ++nt) {
            const int jj0 = nt * 8 + qc;
            float s2v0 = __bfloat162float(*(const __nv_bfloat16*)(sm + SS2 + ((63 + iiA - jj0) * PA + jj0) * 2));
            float s2v1 = __bfloat162float(*(const __nv_bfloat16*)(sm + SS2 + ((62 + iiA - jj0) * PA + jj0 + 1) * 2));
            float s2v2 = __bfloat162float(*(const __nv_bfloat16*)(sm + SS2 + ((63 + iiB - jj0) * PA + jj0) * 2));
            float s2v3 = __bfloat162float(*(const __nv_bfloat16*)(sm + SS2 + ((62 + iiB - jj0) * PA + jj0 + 1) * 2));
            float v0 = (p[nt][0] + s2v0) * 0.125f;
            float v1 = (p[nt][1] + s2v1) * 0.125f;
            float v2 = (p[nt][2] + s2v2) * 0.125f;
            float v3 = (p[nt][3] + s2v3) * 0.125f;
            if (maskt) {
                if (jj0 > iiA + dlt) v0 = -1e30f;
                if (jj0 + 1 > iiA + dlt) v1 = -1e30f;
                if (jj0 > iiB + dlt) v2 = -1e30f;
                if (jj0 + 1 > iiB + dlt) v3 = -1e30f;
            }
            p[nt][0] = v0; p[nt][1] = v1; p[nt][2] = v2; p[nt][3] = v3;
            mx0 = fmaxf(mx0, fmaxf(v0, v1));
            mx1 = fmaxf(mx1, fmaxf(v2, v3));
        }
        mx0 = fmaxf(mx0, __shfl_xor_sync(0xffffffffu, mx0, 1));
        mx0 = fmaxf(mx0, __shfl_xor_sync(0xffffffffu, mx0, 2));
        mx1 = fmaxf(mx1, __shfl_xor_sync(0xffffffffu, mx1, 1));
        mx1 = fmaxf(mx1, __shfl_xor_sync(0xffffffffu, mx1, 2));
        const float mn0 = fmaxf(m0r, mx0), mn1 = fmaxf(m1r, mx1);
        const float c0 = __expf(m0r - mn0), c1 = __expf(m1r - mn1);
        float s0 = 0.f, s1s = 0.f;
#pragma unroll
        for (int nt = 0; nt < 8; ++nt) {
            p[nt][0] = __expf(p[nt][0] - mn0);
            p[nt][1] = __expf(p[nt][1] - mn0);
            p[nt][2] = __expf(p[nt][2] - mn1);
            p[nt][3] = __expf(p[nt][3] - mn1);
            s0 += p[nt][0] + p[nt][1];
            s1s += p[nt][2] + p[nt][3];
        }
        s0 += __shfl_xor_sync(0xffffffffu, s0, 1);
        s0 += __shfl_xor_sync(0xffffffffu, s0, 2);
        s1s += __shfl_xor_sync(0xffffffffu, s1s, 1);
        s1s += __shfl_xor_sync(0xffffffffu, s1s, 2);
        l0r = l0r * c0 + s0;
        l1r = l1r * c1 + s1s;
        m0r = mn0; m1r = mn1;
#pragma unroll
        for (int nt = 0; nt < 8; ++nt) {
            o[nt][0] *= c0; o[nt][1] *= c0;
            o[nt][2] *= c1; o[nt][3] *= c1;
        }
        __syncthreads();   // all S2 reads done before P overwrites the region

        // ---- write P (hi/lo bf16) ----
#pragma unroll
        for (int nt = 0; nt < 8; ++nt) {
            const int col = nt * 8 + qc;
            *(__nv_bfloat162*)(sm + SP_H + (iiA * PA + col) * 2) = split_hi2(p[nt][0], p[nt][1]);
            *(__nv_bfloat162*)(sm + SP_L + (iiA * PA + col) * 2) = split_lo2(p[nt][0], p[nt][1]);
            *(__nv_bfloat162*)(sm + SP_H + (iiB * PA + col) * 2) = split_hi2(p[nt][2], p[nt][3]);
            *(__nv_bfloat162*)(sm + SP_L + (iiB * PA + col) * 2) = split_lo2(p[nt][2], p[nt][3]);
        }
        __syncthreads();   // P visible

        // ---- PV: O += P @ V (3-term) ----
#pragma unroll
        for (int ks = 0; ks < 4; ++ks) {
            uint32_t Ap[4], Apl[4], Vb[4][4], Vbl[4][4];
            ldsm4(Ap,  sb + SP_H + ((w * 16 + a_row) * PA + ks * 16 + a_col) * 2);
            ldsm4(Apl, sb + SP_L + ((w * 16 + a_row) * PA + ks * 16 + a_col) * 2);
#pragma unroll
            for (int nt2 = 0; nt2 < 4; ++nt2) {
                ldsm4(Vb[nt2],  sb + SV_H + ((nt2 * 16 + b_row) * PA + ks * 16 + b_col) * 2);
                ldsm4(Vbl[nt2], sb + SV_L + ((nt2 * 16 + b_row) * PA + ks * 16 + b_col) * 2);
            }
#pragma unroll
            for (int nt = 0; nt < 8; ++nt) {
                mma16816(o[nt], Ap,  &Vb[nt >> 1][(nt & 1) * 2]);
                mma16816(o[nt], Ap,  &Vbl[nt >> 1][(nt & 1) * 2]);
                mma16816(o[nt], Apl, &Vb[nt >> 1][(nt & 1) * 2]);
            }
        }
    }

    // ---- write y (split bf16 directly) ----
    const float iv0 = 1.f / l0r, iv1 = 1.f / l1r;
    const size_t rowA = (size_t)b * T_ + i0 + iiA;
    const size_t rowB = rowA + 8;
#pragma unroll
    for (int nt = 0; nt < 8; ++nt) {
        const int col = h * HD_ + nt * 8 + qc;
        float v0 = o[nt][0] * iv0, v1 = o[nt][1] * iv0;
        float v2 = o[nt][2] * iv1, v3 = o[nt][3] * iv1;
        ((__nv_bfloat162*)g_yh)[(rowA * C_ + col) >> 1] = split_hi2(v0, v1);
        ((__nv_bfloat162*)g_yl)[(rowA * C_ + col) >> 1] = split_lo2(v0, v1);
        ((__nv_bfloat162*)g_yh)[(rowB * C_ + col) >> 1] = split_hi2(v2, v3);
        ((__nv_bfloat162*)g_yl)[(rowB * C_ + col) >> 1] = split_lo2(v2, v3);
    }
}

// ---------------------------------------------------------------------------
// Prep kernels
// ---------------------------------------------------------------------------
__global__ void split_kernel(const float* __restrict__ src,
                             __nv_bfloat16* __restrict__ hi,
                             __nv_bfloat16* __restrict__ lo, int n4)
{
    int i = blockIdx.x * blockDim.x + threadIdx.x;
    if (i >= n4) return;
    float4 v = *(const float4*)(src + (size_t)i * 4);
    ((__nv_bfloat162*)hi)[i * 2 + 0] = split_hi2(v.x, v.y);
    ((__nv_bfloat162*)hi)[i * 2 + 1] = split_hi2(v.z, v.w);
    ((__nv_bfloat162*)lo)[i * 2 + 0] = split_lo2(v.x, v.y);
    ((__nv_bfloat162*)lo)[i * 2 + 1] = split_lo2(v.z, v.w);
}

__global__ void transpose_split_kernel(const float* __restrict__ W,
                                       __nv_bfloat16* __restrict__ th,
                                       __nv_bfloat16* __restrict__ tl, int K, int N)
{
    __shared__ float tile[32][33];
    const int tx = threadIdx.x, ty = threadIdx.y;
    const int n0 = blockIdx.x * 32, k0 = blockIdx.y * 32;
#pragma unroll
    for (int j = 0; j < 4; ++j)
        tile[ty + j * 8][tx] = W[(size_t)(k0 + ty + j * 8) * N + n0 + tx];
    __syncthreads();
#pragma unroll
    for (int j = 0; j < 4; ++j) {
        float v = tile[tx][ty + j * 8];
        __nv_bfloat16 hh = __float2bfloat16(v);
        __nv_bfloat16 ll = __float2bfloat16(v - __bfloat162float(hh));
        size_t o = (size_t)(n0 + ty + j * 8) * K + k0 + tx;
        th[o] = hh; tl[o] = ll;
    }
}

// split qkv into per-head q/k (row) and v (transposed) bf16 hi/lo
__global__ __launch_bounds__(256)
void qkv_split_kernel()
{
    __shared__ float sv[64][65];
    const int tid = threadIdx.x;
    const int bh = blockIdx.y, t0 = blockIdx.x * 64;
    const int b = bh >> 4, h = bh & 15;
    const float* src = g_qkv + ((size_t)(b * T_ + t0)) * C3_ + h * HD_;

#pragma unroll
    for (int u = 0; u < 4; ++u) {
        int idx = u * 256 + tid;
        int r = idx >> 4, c = idx & 15;      // c in float4 units
        float4 q4 = *(const float4*)(src + (size_t)r * C3_ + c * 4);
        float4 k4 = *(const float4*)(src + (size_t)r * C3_ + C_ + c * 4);
        float4 v4 = *(const float4*)(src + (size_t)r * C3_ + 2 * C_ + c * 4);
        size_t oq = (((size_t)bh * T_ + t0 + r) * HD_ + c * 4) >> 1;  // bf162 units
        ((__nv_bfloat162*)g_qh)[oq + 0] = split_hi2(q4.x, q4.y);
        ((__nv_bfloat162*)g_qh)[oq + 1] = split_hi2(q4.z, q4.w);
        ((__nv_bfloat162*)g_ql)[oq + 0] = split_lo2(q4.x, q4.y);
        ((__nv_bfloat162*)g_ql)[oq + 1] = split_lo2(q4.z, q4.w);
        ((__nv_bfloat162*)g_kh)[oq + 0] = split_hi2(k4.x, k4.y);
        ((__nv_bfloat162*)g_kh)[oq + 1] = split_hi2(k4.z, k4.w);
        ((__nv_bfloat162*)g_kl)[oq + 0] = split_lo2(k4.x, k4.y);
        ((__nv_bfloat162*)g_kl)[oq + 1] = split_lo2(k4.z, k4.w);
        sv[r][c * 4 + 0] = v4.x; sv[r][c * 4 + 1] = v4.y;
        sv[r][c * 4 + 2] = v4.z; sv[r][c * 4 + 3] = v4.w;
    }
    __syncthreads();
    // V transpose: 64 d-rows x 4 t-groups = 256 items, exactly one per thread
    {
        int d = tid >> 2, cg = tid & 3;
        size_t ob = (((size_t)bh * HD_ + d) * T_ + t0 + cg * 16) >> 1;  // bf162 units
#pragma unroll
        for (int tt = 0; tt < 16; tt += 2) {
            float v0 = sv[cg * 16 + tt][d], v1 = sv[cg * 16 + tt + 1][d];
            ((__nv_bfloat162*)g_vth)[ob + (tt >> 1)] = split_hi2(v0, v1);
            ((__nv_bfloat162*)g_vtl)[ob + (tt >> 1)] = split_lo2(v0, v1);
        }
    }
}

__global__ void esplit_kernel(const float* __restrict__ rel)
{
    int i = blockIdx.x * blockDim.x + threadIdx.x;   // float4 index
    const int n4 = H_ * T_ * HD_ / 4;
    if (i >= n4) return;
    float4 v = *(const float4*)(rel + (size_t)i * 4);
    ((__nv_bfloat162*)g_eh)[i * 2 + 0] = split_hi2(v.x, v.y);
    ((__nv_bfloat162*)g_eh)[i * 2 + 1] = split_hi2(v.z, v.w);
}

// ---------------------------------------------------------------------------
extern "C" void kernel_launch(void* const* d_in, const int* in_sizes, int n_in,
                              void* d_out, int out_size)
{
    (void)in_sizes; (void)n_in; (void)out_size;
    const float* x      = (const float*)d_in[0];
    const float* W_attn = (const float*)d_in[1];
    const float* b_attn = (const float*)d_in[2];
    const float* W_proj = (const float*)d_in[3];
    const float* b_proj = (const float*)d_in[4];
    const float* rel    = (const float*)d_in[5];
    float* out = (float*)d_out;

    float* qkv = nullptr;
    __nv_bfloat16 *xh, *xl, *yh, *yl, *wah, *wal, *wph, *wpl;
    cudaGetSymbolAddress((void**)&qkv, g_qkv);
    cudaGetSymbolAddress((void**)&xh,  g_xh);
    cudaGetSymbolAddress((void**)&xl,  g_xl);
    cudaGetSymbolAddress((void**)&yh,  g_yh);
    cudaGetSymbolAddress((void**)&yl,  g_yl);
    cudaGetSymbolAddress((void**)&wah, g_wah);
    cudaGetSymbolAddress((void**)&wal, g_wal);
    cudaGetSymbolAddress((void**)&wph, g_wph);
    cudaGetSymbolAddress((void**)&wpl, g_wpl);

    cudaFuncSetAttribute(attn_mma_kernel,
                         cudaFuncAttributeMaxDynamicSharedMemorySize, ATTN_SMEM_BYTES);
    cudaFuncSetAttribute(gemm_mma_kernel,
                         cudaFuncAttributeMaxDynamicSharedMemorySize, GEMM_SMEM_BYTES);

    // prep
    {
        int n4 = B_ * T_ * C_ / 4;
        split_kernel<<<(n4 + 255) / 256, 256>>>(x, xh, xl, n4);
        transpose_split_kernel<<<dim3(C3_ / 32, C_ / 32), dim3(32, 8)>>>(W_attn, wah, wal, C_, C3_);
        transpose_split_kernel<<<dim3(C_ / 32, C_ / 32), dim3(32, 8)>>>(W_proj, wph, wpl, C_, C_);
        int ne4 = H_ * T_ * HD_ / 4;
        esplit_kernel<<<(ne4 + 255) / 256, 256>>>(rel);
    }

    // 1) qkv = x @ W_attn + b_attn
    gemm_mma_kernel<<<dim3(C3_ / 128, (B_ * T_) / 128), 256, GEMM_SMEM_BYTES>>>(
        xh, xl, wah, wal, b_attn, qkv, B_ * T_, C3_, C_);

    // 2) per-head split (+ V transpose)
    qkv_split_kernel<<<dim3(T_ / 64, B_ * H_), 256>>>();

    // 3) MMA flash attention (i-tile 128) -> yh/yl
    attn_mma_kernel<<<dim3(B_ * H_, T_ / 128), 256, ATTN_SMEM_BYTES>>>();

    // 4) out = y @ W_proj + b_proj
    gemm_mma_kernel<<<dim3(C_ / 128, (B_ * T_) / 128), 256, GEMM_SMEM_BYTES>>>(
        yh, yl, wph, wpl, b_proj, out, B_ * T_, C_, C_);
}